// round 5
// baseline (speedup 1.0000x reference)
#include <cuda_runtime.h>
#include <cuda.h>
#include <cuda_fp16.h>
#include <cstdint>
#include <cstdio>

// ============================================================================
// Problem dims
// ============================================================================
#define M_DIM 8192
#define N_DIM 4096
#define K_DIM 4096
#define LORA_R 8
#define SCALE_F 2.0f

// cg1 tiling: CTA tile 256x256 (2 M-halves x 2 N-halves of 128), BK=64
#define BM 256
#define BN 256
#define BK 64
#define STAGES 3
#define KTILES (K_DIM / BK)

// Scratch (device globals: no runtime allocation)
__device__ __half g_xh[(size_t)M_DIM * K_DIM];   // x in fp16, row-major [M, K]
__device__ __half g_wh[(size_t)N_DIM * K_DIM];   // W' = base + 2*(B@A) fp16, [N, K]

// ============================================================================
// Common helpers
// ============================================================================
__device__ __forceinline__ uint32_t smem_u32(const void* p) {
    uint32_t a;
    asm("{ .reg .u64 t; cvta.to.shared.u64 t, %1; cvt.u32.u64 %0, t; }"
        : "=r"(a) : "l"(p));
    return a;
}

// ---------------- sm_103a-only helpers -------------------------------------
#define MBARRIER_INIT(addr, count) \
    asm volatile("mbarrier.init.shared.b64 [%0], %1;" :: "r"((uint32_t)(addr)), "r"((uint32_t)(count)) : "memory")

#define MBARRIER_EXPECT_TX(addr, bytes) \
    asm volatile("mbarrier.arrive.expect_tx.shared.b64 _, [%0], %1;" :: "r"((uint32_t)(addr)), "r"((uint32_t)(bytes)) : "memory")

#define MBARRIER_WAIT_PARITY(mbar_addr, phase_parity) do { \
    uint32_t _mbar = (uint32_t)(mbar_addr); \
    uint32_t _parity = (uint32_t)(phase_parity); \
    uint32_t _done; \
    asm volatile( \
        "{\n\t.reg .pred p;\n\t" \
        "mbarrier.try_wait.parity.acquire.cta.shared::cta.b64 p, [%1], %2;\n\t" \
        "selp.b32 %0, 1, 0, p;\n\t}" \
        : "=r"(_done) : "r"(_mbar), "r"(_parity) : "memory"); \
    if (!_done) { \
        asm volatile( \
            "{\n\t.reg .pred P1;\n\t" \
            "WAIT_LOOP_%=:\n\t" \
            "mbarrier.try_wait.parity.acquire.cta.shared::cta.b64 P1, [%0], %1, 0x989680;\n\t" \
            "@P1 bra.uni WAIT_DONE_%=;\n\t" \
            "bra.uni WAIT_LOOP_%=;\n\t" \
            "WAIT_DONE_%=:\n\t}" \
            :: "r"(_mbar), "r"(_parity) : "memory"); \
    } \
} while (0)

#define TCGEN05_ALLOC(smem_addr, nCols) \
    asm volatile("tcgen05.alloc.cta_group::1.sync.aligned.shared::cta.b32 [%0], %1;" \
                 :: "r"((uint32_t)(smem_addr)), "r"((uint32_t)(nCols)) : "memory")

#define TCGEN05_DEALLOC(tmem_addr, nCols) \
    asm volatile("tcgen05.dealloc.cta_group::1.sync.aligned.b32 %0, %1;" \
                 :: "r"(tmem_addr), "r"((uint32_t)(nCols)))

#define TCGEN05_RELINQUISH() \
    asm volatile("tcgen05.relinquish_alloc_permit.cta_group::1.sync.aligned;")

#define TCGEN05_COMMIT(mbar_addr) \
    asm volatile("tcgen05.commit.cta_group::1.mbarrier::arrive::one.shared::cluster.b64 [%0];" \
                 :: "r"((uint32_t)(mbar_addr)) : "memory")

#define TCGEN05_FENCE_AFTER()  asm volatile("tcgen05.fence::after_thread_sync;" ::: "memory")
#define TCGEN05_FENCE_BEFORE() asm volatile("tcgen05.fence::before_thread_sync;" ::: "memory")
#define TCGEN05_WAIT_LD()      asm volatile("tcgen05.wait::ld.sync.aligned;" ::: "memory")

#define TCGEN05_LD_32X32B_X32(r, tmem_addr) \
    asm volatile( \
        "tcgen05.ld.sync.aligned.32x32b.x32.b32 " \
        "{%0, %1, %2, %3, %4, %5, %6, %7, " \
        " %8, %9, %10, %11, %12, %13, %14, %15, " \
        " %16, %17, %18, %19, %20, %21, %22, %23, " \
        " %24, %25, %26, %27, %28, %29, %30, %31}, [%32];" \
        : "=r"((r)[0]),  "=r"((r)[1]),  "=r"((r)[2]),  "=r"((r)[3]), \
          "=r"((r)[4]),  "=r"((r)[5]),  "=r"((r)[6]),  "=r"((r)[7]), \
          "=r"((r)[8]),  "=r"((r)[9]),  "=r"((r)[10]), "=r"((r)[11]), \
          "=r"((r)[12]), "=r"((r)[13]), "=r"((r)[14]), "=r"((r)[15]), \
          "=r"((r)[16]), "=r"((r)[17]), "=r"((r)[18]), "=r"((r)[19]), \
          "=r"((r)[20]), "=r"((r)[21]), "=r"((r)[22]), "=r"((r)[23]), \
          "=r"((r)[24]), "=r"((r)[25]), "=r"((r)[26]), "=r"((r)[27]), \
          "=r"((r)[28]), "=r"((r)[29]), "=r"((r)[30]), "=r"((r)[31]) \
        : "r"(tmem_addr))

// K-major SW128 SMEM descriptor (LBO=1, SBO=64, version=1, layout=SW128)
static constexpr uint64_t SMEM_DESC_BASE_SW128 =
    (uint64_t(2) << 61) | (uint64_t(1) << 46) | (uint64_t(64) << 32) | (uint64_t(1) << 16);

#define MAKE_SMEM_DESC(base_addr) \
    (SMEM_DESC_BASE_SW128 | ((uint64_t)((base_addr) >> 4) & 0x3FFF))

#define TMA_LOAD_2D(dst, map, cx, cy, mbar) \
    asm volatile( \
        "cp.async.bulk.tensor.2d.shared::cta.global.tile.mbarrier::complete_tx::bytes " \
        "[%0], [%1, {%2, %3}], [%4];" \
        :: "r"((uint32_t)(dst)), "l"(map), "r"((int)(cx)), "r"((int)(cy)), "r"((uint32_t)(mbar)) : "memory")

// ============================================================================
// Preprocessing kernels (arch-independent)
// ============================================================================
__global__ void convert_x_kernel(const float4* __restrict__ x, uint2* __restrict__ xh, int n4) {
    int i = blockIdx.x * blockDim.x + threadIdx.x;
    int half_n = n4 >> 1;
    if (i >= half_n) return;
#pragma unroll
    for (int t = 0; t < 2; t++) {
        int idx = i + t * half_n;
        float4 v = x[idx];
        __half2 a = __floats2half2_rn(v.x, v.y);
        __half2 b = __floats2half2_rn(v.z, v.w);
        uint2 u;
        u.x = *reinterpret_cast<uint32_t*>(&a);
        u.y = *reinterpret_cast<uint32_t*>(&b);
        xh[idx] = u;
    }
}

// W'[o,k] = base[o,k] + SCALE * sum_r B[o,r]*A[r,k], fp16 output
__global__ void build_w_kernel(const float4* __restrict__ base, const float4* __restrict__ A,
                               const float* __restrict__ B, uint2* __restrict__ wh) {
    int idx = blockIdx.x * blockDim.x + threadIdx.x;   // over N_DIM * K_DIM/4
    if (idx >= N_DIM * (K_DIM / 4)) return;
    int o = idx / (K_DIM / 4);
    int kq = idx - o * (K_DIM / 4);
    float4 acc = base[idx];
#pragma unroll
    for (int r = 0; r < LORA_R; r++) {
        float b = SCALE_F * __ldg(&B[o * LORA_R + r]);
        float4 a = __ldg(&A[r * (K_DIM / 4) + kq]);
        acc.x = fmaf(b, a.x, acc.x);
        acc.y = fmaf(b, a.y, acc.y);
        acc.z = fmaf(b, a.z, acc.z);
        acc.w = fmaf(b, a.w, acc.w);
    }
    __half2 h0 = __floats2half2_rn(acc.x, acc.y);
    __half2 h1 = __floats2half2_rn(acc.z, acc.w);
    uint2 u;
    u.x = *reinterpret_cast<uint32_t*>(&h0);
    u.y = *reinterpret_cast<uint32_t*>(&h1);
    wh[idx] = u;
}

// ============================================================================
// GEMM kernel: out[m,n] = sum_k xh[m,k]*wh[n,k] + bias[n]
//   sm_103a pass -> cg1 tcgen05, 256x256 tile, TMA pipeline
//   plain compute_103 -> mma.sync fallback
// ============================================================================
static constexpr int A_HALF   = 128 * BK * 2;            // 16384 (one A m-half)
static constexpr int B_HALF   = 128 * BK * 2;            // 16384 (one B n-half)
static constexpr int STG_BYTES = 2 * A_HALF + 2 * B_HALF; // 65536
static constexpr int SMEM_TMEMPTR = 0;
static constexpr int SMEM_BAR = 16;                      // full[s]=+8s, empty[s]=+32+8s, done=+64
static constexpr int SMEM_TILES = 1024;
static constexpr int GEMM_SMEM = SMEM_TILES + STAGES * STG_BYTES;  // 197632

// idesc for cg1 kind::f16, fp32 accum, M=128, N=128
static constexpr uint32_t GEMM_IDESC_N128 =
    (1u << 4) | ((128 / 8) << 17) | ((128 / 16) << 24);

// ---- fallback constants ----
static constexpr int FB_ROWB  = 144;              // 64 halves + 8 pad halves, bytes
static constexpr int FB_TILE  = 128 * FB_ROWB;    // 18432 per A or B tile
static constexpr int FB_STAGE = 2 * FB_TILE;      // 36864 per stage

#if !defined(__CUDA_ARCH__) || !defined(__CUDA_ARCH_FEAT_SM103_ALL)
__device__ __forceinline__ void cp_async16(uint32_t dst, const void* src) {
    asm volatile("cp.async.cg.shared.global [%0], [%1], 16;" :: "r"(dst), "l"(src) : "memory");
}
__device__ __forceinline__ void ldsm_x4(uint32_t* r, uint32_t addr) {
    asm volatile("ldmatrix.sync.aligned.m8n8.x4.shared.b16 {%0,%1,%2,%3}, [%4];"
                 : "=r"(r[0]), "=r"(r[1]), "=r"(r[2]), "=r"(r[3]) : "r"(addr));
}
__device__ __forceinline__ void mma16816(float* c, const uint32_t* a, uint32_t b0, uint32_t b1) {
    asm volatile("mma.sync.aligned.m16n8k16.row.col.f32.f16.f16.f32 "
                 "{%0,%1,%2,%3}, {%4,%5,%6,%7}, {%8,%9}, {%0,%1,%2,%3};"
                 : "+f"(c[0]), "+f"(c[1]), "+f"(c[2]), "+f"(c[3])
                 : "r"(a[0]), "r"(a[1]), "r"(a[2]), "r"(a[3]), "r"(b0), "r"(b1));
}
#endif

__global__ void __launch_bounds__(128, 1) lora_gemm_kernel(
    const __grid_constant__ CUtensorMap tmap_a,
    const __grid_constant__ CUtensorMap tmap_b,
    const __half* __restrict__ xh,
    const __half* __restrict__ wh,
    const float* __restrict__ bias,
    float* __restrict__ out)
{
    extern __shared__ __align__(1024) char smem[];
    const uint32_t sb = smem_u32(smem);
    const int tid = threadIdx.x;
    const int wid = tid >> 5;
    const int lane = tid & 31;
    const int m0 = blockIdx.y * BM;
    const int n0 = blockIdx.x * BN;

#if defined(__CUDA_ARCH_FEAT_SM103_ALL)
    // =========================== tcgen05 path ===============================
    if (wid == 0) {
        TCGEN05_ALLOC(sb + SMEM_TMEMPTR, 512);
        TCGEN05_RELINQUISH();
    }
    if (tid == 0) {
#pragma unroll
        for (int s = 0; s < STAGES; s++) {
            MBARRIER_INIT(sb + SMEM_BAR + 8 * s, 1);       // full
            MBARRIER_INIT(sb + SMEM_BAR + 32 + 8 * s, 1);  // empty
        }
        MBARRIER_INIT(sb + SMEM_BAR + 64, 1);              // done
    }
    __syncthreads();
    TCGEN05_FENCE_AFTER();

    uint32_t tmem;
    asm volatile("ld.shared.b32 %0, [%1];" : "=r"(tmem) : "r"(sb + SMEM_TMEMPTR));

    if (wid == 1) {
        // ---- TMA producer warp ----
        uint32_t elected;
        asm volatile("{\n\t.reg .pred P;\n\telect.sync _|P, 0xFFFFFFFF;\n\tselp.b32 %0, 1, 0, P;\n\t}"
                     : "=r"(elected));
        int s = 0, ph = 1;  // fresh barrier satisfies first wait(parity=1)
        for (int kt = 0; kt < KTILES; kt++) {
            MBARRIER_WAIT_PARITY(sb + SMEM_BAR + 32 + 8 * s, ph);
            if (elected) {
                uint32_t full = sb + SMEM_BAR + 8 * s;
                MBARRIER_EXPECT_TX(full, STG_BYTES);
                uint32_t dst = sb + SMEM_TILES + s * STG_BYTES;
                TMA_LOAD_2D(dst,              &tmap_a, kt * BK, m0,        full);
                TMA_LOAD_2D(dst + A_HALF,     &tmap_a, kt * BK, m0 + 128,  full);
                TMA_LOAD_2D(dst + 2 * A_HALF, &tmap_b, kt * BK, n0,        full);
                TMA_LOAD_2D(dst + 2 * A_HALF + B_HALF, &tmap_b, kt * BK, n0 + 128, full);
            }
            if (++s == STAGES) { s = 0; ph ^= 1; }
        }
    } else if (wid == 0) {
        // ---- MMA warp: 16 x (128x128x16) MMAs per ktile into 4 D regions ----
        uint32_t elected;
        asm volatile("{\n\t.reg .pred P;\n\telect.sync _|P, 0xFFFFFFFF;\n\tselp.b32 %0, 1, 0, P;\n\t}"
                     : "=r"(elected));
        int s = 0, ph = 0;
        for (int kt = 0; kt < KTILES; kt++) {
            MBARRIER_WAIT_PARITY(sb + SMEM_BAR + 8 * s, ph);
            if (elected) {
                uint32_t stg = sb + SMEM_TILES + s * STG_BYTES;
                uint64_t ad0 = MAKE_SMEM_DESC(stg);
                uint64_t ad1 = MAKE_SMEM_DESC(stg + A_HALF);
                uint64_t bd0 = MAKE_SMEM_DESC(stg + 2 * A_HALF);
                uint64_t bd1 = MAKE_SMEM_DESC(stg + 2 * A_HALF + B_HALF);
                uint32_t en0 = (kt == 0) ? 0u : 1u;
#pragma unroll
                for (int j = 0; j < BK / 16; j++) {
                    uint32_t en = (j == 0) ? en0 : 1u;
                    uint32_t zero = 0u;
                    uint64_t aj0 = ad0 + j * 2, aj1 = ad1 + j * 2;
                    uint64_t bj0 = bd0 + j * 2, bj1 = bd1 + j * 2;
                    // D regions: (mh, nh) -> tmem + mh*256 + nh*128
#define MMA_ONE(doff, adesc, bdesc) \
                    asm volatile( \
                        "{\n\t.reg .pred p;\n\tsetp.ne.u32 p, %5, 0;\n\t" \
                        "tcgen05.mma.cta_group::1.kind::f16 [%0], %1, %2, %3, {%4, %4, %4, %4}, p;\n\t}" \
                        :: "r"(tmem + (doff)), "l"(adesc), "l"(bdesc), \
                           "r"(GEMM_IDESC_N128), "r"(zero), "r"(en) : "memory")
                    MMA_ONE(0,   aj0, bj0);
                    MMA_ONE(128, aj0, bj1);
                    MMA_ONE(256, aj1, bj0);
                    MMA_ONE(384, aj1, bj1);
#undef MMA_ONE
                }
                TCGEN05_COMMIT(sb + SMEM_BAR + 32 + 8 * s);  // stage reusable
            }
            if (++s == STAGES) { s = 0; ph ^= 1; }
        }
        if (elected) {
            TCGEN05_COMMIT(sb + SMEM_BAR + 64);  // all MMAs done
        }
    }

    // ---- all warps: wait for GEMM completion ----
    MBARRIER_WAIT_PARITY(sb + SMEM_BAR + 64, 0);
    TCGEN05_FENCE_AFTER();

    // ---- epilogue: per M-half, TMEM -> padded smem -> coalesced gmem ----
    float* eb = reinterpret_cast<float*>(smem + SMEM_TILES);  // 128 x 257 floats
    const int row = wid * 32 + lane;
#pragma unroll
    for (int mh = 0; mh < 2; mh++) {
#pragma unroll
        for (int cb = 0; cb < BN / 32; cb++) {
            uint32_t r[32];
            TCGEN05_LD_32X32B_X32(r, tmem + mh * 256 + cb * 32);
            TCGEN05_WAIT_LD();
#pragma unroll
            for (int c = 0; c < 32; c++)
                eb[row * (BN + 1) + cb * 32 + c] = __uint_as_float(r[c]);
        }
        TCGEN05_FENCE_BEFORE();
        __syncthreads();

        for (int idx = tid; idx < 128 * (BN / 4); idx += 128) {
            int r_ = idx >> 6;       // 64 float4 per row
            int c4 = idx & 63;
            int col = c4 << 2;
            const float* p = &eb[r_ * (BN + 1) + col];
            float4 v;
            v.x = p[0] + __ldg(&bias[n0 + col + 0]);
            v.y = p[1] + __ldg(&bias[n0 + col + 1]);
            v.z = p[2] + __ldg(&bias[n0 + col + 2]);
            v.w = p[3] + __ldg(&bias[n0 + col + 3]);
            *reinterpret_cast<float4*>(
                &out[(size_t)(m0 + mh * 128 + r_) * N_DIM + n0 + col]) = v;
        }
        __syncthreads();  // buffer reuse between halves
    }

    if (wid == 0) {
        TCGEN05_DEALLOC(tmem, 512);
    }

#else
    // ======================= mma.sync fallback path ==========================
    // CTA tile 256x256 as four 128x128 quadrants; 4 warps, warp tile 64x64.
    (void)tmap_a; (void)tmap_b;
    const int wm = (wid >> 1) * 64;
    const int wn = (wid & 1) * 64;
    const int l = lane;
    const int a_r = (l & 7) + ((l >> 3) & 1) * 8;
    const int a_c = (l >> 4) * 8;
    const int b_r = (l & 7) + ((l >> 4) & 1) * 8;
    const int b_c = ((l >> 3) & 1) * 8;

    for (int mh = 0; mh < 2; mh++)
    for (int nh = 0; nh < 2; nh++) {
        const int mb0 = m0 + mh * 128;
        const int nb0 = n0 + nh * 128;
        float acc[4][8][4];
#pragma unroll
        for (int mt = 0; mt < 4; mt++)
#pragma unroll
            for (int nt = 0; nt < 8; nt++)
#pragma unroll
                for (int i = 0; i < 4; i++) acc[mt][nt][i] = 0.0f;

        {
            const __half* ga = xh + (size_t)(mb0 + tid) * K_DIM;
            const __half* gb = wh + (size_t)(nb0 + tid) * K_DIM;
            uint32_t da = sb + tid * FB_ROWB;
            uint32_t db = sb + FB_TILE + tid * FB_ROWB;
#pragma unroll
            for (int i = 0; i < 8; i++) {
                cp_async16(da + i * 16, ga + i * 8);
                cp_async16(db + i * 16, gb + i * 8);
            }
            asm volatile("cp.async.commit_group;" ::: "memory");
        }

        for (int kt = 0; kt < KTILES; kt++) {
            if (kt + 1 < KTILES) {
                int s = (kt + 1) & 1;
                const __half* ga = xh + (size_t)(mb0 + tid) * K_DIM + (kt + 1) * BK;
                const __half* gb = wh + (size_t)(nb0 + tid) * K_DIM + (kt + 1) * BK;
                uint32_t da = sb + s * FB_STAGE + tid * FB_ROWB;
                uint32_t db = sb + s * FB_STAGE + FB_TILE + tid * FB_ROWB;
#pragma unroll
                for (int i = 0; i < 8; i++) {
                    cp_async16(da + i * 16, ga + i * 8);
                    cp_async16(db + i * 16, gb + i * 8);
                }
                asm volatile("cp.async.commit_group;" ::: "memory");
                asm volatile("cp.async.wait_group 1;" ::: "memory");
            } else {
                asm volatile("cp.async.wait_group 0;" ::: "memory");
            }
            __syncthreads();

            uint32_t sA = sb + (kt & 1) * FB_STAGE;
            uint32_t sB = sA + FB_TILE;
#pragma unroll
            for (int ks = 0; ks < BK / 16; ks++) {
                uint32_t afrag[4][4];
#pragma unroll
                for (int mt = 0; mt < 4; mt++) {
                    uint32_t addr = sA + (wm + mt * 16 + a_r) * FB_ROWB + (ks * 16 + a_c) * 2;
                    ldsm_x4(afrag[mt], addr);
                }
                uint32_t bfrag[4][4];
#pragma unroll
                for (int p = 0; p < 4; p++) {
                    uint32_t addr = sB + (wn + p * 16 + b_r) * FB_ROWB + (ks * 16 + b_c) * 2;
                    ldsm_x4(bfrag[p], addr);
                }
#pragma unroll
                for (int mt = 0; mt < 4; mt++)
#pragma unroll
                    for (int nt = 0; nt < 8; nt++)
                        mma16816(acc[mt][nt], afrag[mt],
                                 bfrag[nt >> 1][(nt & 1) * 2], bfrag[nt >> 1][(nt & 1) * 2 + 1]);
            }
            __syncthreads();
        }

#pragma unroll
        for (int mt = 0; mt < 4; mt++) {
#pragma unroll
            for (int nt = 0; nt < 8; nt++) {
                int r0 = mb0 + wm + mt * 16 + (l >> 2);
                int c0 = nb0 + wn + nt * 8 + (l & 3) * 2;
                float bx = __ldg(&bias[c0]);
                float by = __ldg(&bias[c0 + 1]);
                float2 v0 = make_float2(acc[mt][nt][0] + bx, acc[mt][nt][1] + by);
                float2 v1 = make_float2(acc[mt][nt][2] + bx, acc[mt][nt][3] + by);
                *reinterpret_cast<float2*>(&out[(size_t)r0 * N_DIM + c0]) = v0;
                *reinterpret_cast<float2*>(&out[(size_t)(r0 + 8) * N_DIM + c0]) = v1;
            }
        }
    }
#endif
}

// ============================================================================
// Host launch
// ============================================================================
typedef CUresult (*tmap_encode_t)(CUtensorMap*, CUtensorMapDataType, cuuint32_t, void*,
                                  const cuuint64_t*, const cuuint64_t*, const cuuint32_t*,
                                  const cuuint32_t*, CUtensorMapInterleave, CUtensorMapSwizzle,
                                  CUtensorMapL2promotion, CUtensorMapFloatOOBfill);

extern "C" void kernel_launch(void* const* d_in, const int* in_sizes, int n_in,
                              void* d_out, int out_size) {
    (void)in_sizes; (void)n_in; (void)out_size;
    const float* x    = (const float*)d_in[0];
    const float* base = (const float*)d_in[1];
    const float* lA   = (const float*)d_in[2];
    const float* lB   = (const float*)d_in[3];
    const float* bias = (const float*)d_in[4];
    float* out = (float*)d_out;

    void* xh_p = nullptr;
    void* wh_p = nullptr;
    cudaGetSymbolAddress(&xh_p, g_xh);
    cudaGetSymbolAddress(&wh_p, g_wh);

    // 1) x -> fp16
    {
        int n4 = M_DIM * K_DIM / 4;
        int nthreads = n4 / 2;
        convert_x_kernel<<<(nthreads + 255) / 256, 256>>>((const float4*)x, (uint2*)xh_p, n4);
    }
    // 2) W' = base + 2*(B@A) -> fp16
    {
        int n4 = N_DIM * K_DIM / 4;
        build_w_kernel<<<(n4 + 255) / 256, 256>>>((const float4*)base, (const float4*)lA,
                                                  lB, (uint2*)wh_p);
    }

    // 3) tensor maps (A and B boxes 64 x 128 rows)
    static tmap_encode_t encode = nullptr;
    if (!encode) {
        void* pfn = nullptr;
        cudaDriverEntryPointQueryResult qres;
#if CUDART_VERSION >= 12050
        cudaGetDriverEntryPointByVersion("cuTensorMapEncodeTiled", &pfn, 12000,
                                         cudaEnableDefault, &qres);
#else
        cudaGetDriverEntryPoint("cuTensorMapEncodeTiled", &pfn, cudaEnableDefault, &qres);
#endif
        encode = (tmap_encode_t)pfn;
    }

    CUtensorMap mapA{}, mapB{};
    if (encode) {
        {
            cuuint64_t dims[2]    = {K_DIM, M_DIM};
            cuuint64_t strides[1] = {K_DIM * sizeof(__half)};
            cuuint32_t box[2]     = {BK, 128};
            cuuint32_t es[2]      = {1, 1};
            encode(&mapA, CU_TENSOR_MAP_DATA_TYPE_FLOAT16, 2, xh_p, dims, strides, box, es,
                   CU_TENSOR_MAP_INTERLEAVE_NONE, CU_TENSOR_MAP_SWIZZLE_128B,
                   CU_TENSOR_MAP_L2_PROMOTION_L2_128B, CU_TENSOR_MAP_FLOAT_OOB_FILL_NONE);
        }
        {
            cuuint64_t dims[2]    = {K_DIM, N_DIM};
            cuuint64_t strides[1] = {K_DIM * sizeof(__half)};
            cuuint32_t box[2]     = {BK, 128};
            cuuint32_t es[2]      = {1, 1};
            encode(&mapB, CU_TENSOR_MAP_DATA_TYPE_FLOAT16, 2, wh_p, dims, strides, box, es,
                   CU_TENSOR_MAP_INTERLEAVE_NONE, CU_TENSOR_MAP_SWIZZLE_128B,
                   CU_TENSOR_MAP_L2_PROMOTION_L2_128B, CU_TENSOR_MAP_FLOAT_OOB_FILL_NONE);
        }
    }

    cudaFuncSetAttribute(lora_gemm_kernel, cudaFuncAttributeMaxDynamicSharedMemorySize,
                         GEMM_SMEM);
    dim3 grid(N_DIM / BN, M_DIM / BM);  // (16, 32) = 512 CTAs
    lora_gemm_kernel<<<grid, 128, GEMM_SMEM>>>(mapA, mapB,
                                               (const __half*)xh_p, (const __half*)wh_p,
                                               bias, out);
}

// round 6
// speedup vs baseline: 1.0160x; 1.0160x over previous
#include <cuda_runtime.h>
#include <cuda.h>
#include <cuda_fp16.h>
#include <cstdint>
#include <cstdio>

// ============================================================================
// Problem dims
// ============================================================================
#define M_DIM 8192
#define N_DIM 4096
#define K_DIM 4096
#define LORA_R 8
#define SCALE_F 2.0f

// Persistent tiling: tile 256(M) x 128(N), BK=64, 1024 tiles over 148 CTAs
#define TM 256
#define TN 128
#define BK 64
#define STAGES 4
#define KTILES (K_DIM / BK)
#define NTILES ((M_DIM / TM) * (N_DIM / TN))   // 32*32 = 1024
#define NT_CNT (N_DIM / TN)                    // 32
#define GRID_X 148

// Scratch (device globals: no runtime allocation)
__device__ __half g_xh[(size_t)M_DIM * K_DIM];   // x in fp16, row-major [M, K]
__device__ __half g_wh[(size_t)N_DIM * K_DIM];   // W' = base + 2*(B@A) fp16, [N, K]

// ============================================================================
// Common helpers
// ============================================================================
__device__ __forceinline__ uint32_t smem_u32(const void* p) {
    uint32_t a;
    asm("{ .reg .u64 t; cvta.to.shared.u64 t, %1; cvt.u32.u64 %0, t; }"
        : "=r"(a) : "l"(p));
    return a;
}

// ---------------- sm_103a-only helpers -------------------------------------
#define MBARRIER_INIT(addr, count) \
    asm volatile("mbarrier.init.shared.b64 [%0], %1;" :: "r"((uint32_t)(addr)), "r"((uint32_t)(count)) : "memory")

#define MBARRIER_EXPECT_TX(addr, bytes) \
    asm volatile("mbarrier.arrive.expect_tx.shared.b64 _, [%0], %1;" :: "r"((uint32_t)(addr)), "r"((uint32_t)(bytes)) : "memory")

#define MBARRIER_ARRIVE(addr) \
    asm volatile("mbarrier.arrive.shared.b64 _, [%0];" :: "r"((uint32_t)(addr)) : "memory")

#define MBARRIER_WAIT_PARITY(mbar_addr, phase_parity) do { \
    uint32_t _mbar = (uint32_t)(mbar_addr); \
    uint32_t _parity = (uint32_t)(phase_parity); \
    uint32_t _done; \
    asm volatile( \
        "{\n\t.reg .pred p;\n\t" \
        "mbarrier.try_wait.parity.acquire.cta.shared::cta.b64 p, [%1], %2;\n\t" \
        "selp.b32 %0, 1, 0, p;\n\t}" \
        : "=r"(_done) : "r"(_mbar), "r"(_parity) : "memory"); \
    if (!_done) { \
        asm volatile( \
            "{\n\t.reg .pred P1;\n\t" \
            "WAIT_LOOP_%=:\n\t" \
            "mbarrier.try_wait.parity.acquire.cta.shared::cta.b64 P1, [%0], %1, 0x989680;\n\t" \
            "@P1 bra.uni WAIT_DONE_%=;\n\t" \
            "bra.uni WAIT_LOOP_%=;\n\t" \
            "WAIT_DONE_%=:\n\t}" \
            :: "r"(_mbar), "r"(_parity) : "memory"); \
    } \
} while (0)

#define TCGEN05_ALLOC(smem_addr, nCols) \
    asm volatile("tcgen05.alloc.cta_group::1.sync.aligned.shared::cta.b32 [%0], %1;" \
                 :: "r"((uint32_t)(smem_addr)), "r"((uint32_t)(nCols)) : "memory")

#define TCGEN05_DEALLOC(tmem_addr, nCols) \
    asm volatile("tcgen05.dealloc.cta_group::1.sync.aligned.b32 %0, %1;" \
                 :: "r"(tmem_addr), "r"((uint32_t)(nCols)))

#define TCGEN05_RELINQUISH() \
    asm volatile("tcgen05.relinquish_alloc_permit.cta_group::1.sync.aligned;")

#define TCGEN05_COMMIT(mbar_addr) \
    asm volatile("tcgen05.commit.cta_group::1.mbarrier::arrive::one.shared::cluster.b64 [%0];" \
                 :: "r"((uint32_t)(mbar_addr)) : "memory")

#define TCGEN05_FENCE_AFTER()  asm volatile("tcgen05.fence::after_thread_sync;" ::: "memory")
#define TCGEN05_FENCE_BEFORE() asm volatile("tcgen05.fence::before_thread_sync;" ::: "memory")
#define TCGEN05_WAIT_LD()      asm volatile("tcgen05.wait::ld.sync.aligned;" ::: "memory")

#define TCGEN05_LD_32X32B_X32(r, tmem_addr) \
    asm volatile( \
        "tcgen05.ld.sync.aligned.32x32b.x32.b32 " \
        "{%0, %1, %2, %3, %4, %5, %6, %7, " \
        " %8, %9, %10, %11, %12, %13, %14, %15, " \
        " %16, %17, %18, %19, %20, %21, %22, %23, " \
        " %24, %25, %26, %27, %28, %29, %30, %31}, [%32];" \
        : "=r"((r)[0]),  "=r"((r)[1]),  "=r"((r)[2]),  "=r"((r)[3]), \
          "=r"((r)[4]),  "=r"((r)[5]),  "=r"((r)[6]),  "=r"((r)[7]), \
          "=r"((r)[8]),  "=r"((r)[9]),  "=r"((r)[10]), "=r"((r)[11]), \
          "=r"((r)[12]), "=r"((r)[13]), "=r"((r)[14]), "=r"((r)[15]), \
          "=r"((r)[16]), "=r"((r)[17]), "=r"((r)[18]), "=r"((r)[19]), \
          "=r"((r)[20]), "=r"((r)[21]), "=r"((r)[22]), "=r"((r)[23]), \
          "=r"((r)[24]), "=r"((r)[25]), "=r"((r)[26]), "=r"((r)[27]), \
          "=r"((r)[28]), "=r"((r)[29]), "=r"((r)[30]), "=r"((r)[31]) \
        : "r"(tmem_addr))

// K-major SW128 SMEM descriptor (LBO=1, SBO=64, version=1, layout=SW128)
static constexpr uint64_t SMEM_DESC_BASE_SW128 =
    (uint64_t(2) << 61) | (uint64_t(1) << 46) | (uint64_t(64) << 32) | (uint64_t(1) << 16);

#define MAKE_SMEM_DESC(base_addr) \
    (SMEM_DESC_BASE_SW128 | ((uint64_t)((base_addr) >> 4) & 0x3FFF))

#define TMA_LOAD_2D(dst, map, cx, cy, mbar) \
    asm volatile( \
        "cp.async.bulk.tensor.2d.shared::cta.global.tile.mbarrier::complete_tx::bytes " \
        "[%0], [%1, {%2, %3}], [%4];" \
        :: "r"((uint32_t)(dst)), "l"(map), "r"((int)(cx)), "r"((int)(cy)), "r"((uint32_t)(mbar)) : "memory")

// ============================================================================
// Preprocessing kernels (arch-independent)
// ============================================================================
__global__ void convert_x_kernel(const float4* __restrict__ x, uint2* __restrict__ xh, int n4) {
    int i = blockIdx.x * blockDim.x + threadIdx.x;
    int half_n = n4 >> 1;
    if (i >= half_n) return;
#pragma unroll
    for (int t = 0; t < 2; t++) {
        int idx = i + t * half_n;
        float4 v = x[idx];
        __half2 a = __floats2half2_rn(v.x, v.y);
        __half2 b = __floats2half2_rn(v.z, v.w);
        uint2 u;
        u.x = *reinterpret_cast<uint32_t*>(&a);
        u.y = *reinterpret_cast<uint32_t*>(&b);
        xh[idx] = u;
    }
}

// W'[o,k] = base[o,k] + SCALE * sum_r B[o,r]*A[r,k], fp16 output
__global__ void build_w_kernel(const float4* __restrict__ base, const float4* __restrict__ A,
                               const float* __restrict__ B, uint2* __restrict__ wh) {
    int idx = blockIdx.x * blockDim.x + threadIdx.x;   // over N_DIM * K_DIM/4
    if (idx >= N_DIM * (K_DIM / 4)) return;
    int o = idx / (K_DIM / 4);
    int kq = idx - o * (K_DIM / 4);
    float4 acc = base[idx];
#pragma unroll
    for (int r = 0; r < LORA_R; r++) {
        float b = SCALE_F * __ldg(&B[o * LORA_R + r]);
        float4 a = __ldg(&A[r * (K_DIM / 4) + kq]);
        acc.x = fmaf(b, a.x, acc.x);
        acc.y = fmaf(b, a.y, acc.y);
        acc.z = fmaf(b, a.z, acc.z);
        acc.w = fmaf(b, a.w, acc.w);
    }
    __half2 h0 = __floats2half2_rn(acc.x, acc.y);
    __half2 h1 = __floats2half2_rn(acc.z, acc.w);
    uint2 u;
    u.x = *reinterpret_cast<uint32_t*>(&h0);
    u.y = *reinterpret_cast<uint32_t*>(&h1);
    wh[idx] = u;
}

// ============================================================================
// Persistent GEMM kernel: out[m,n] = sum_k xh[m,k]*wh[n,k] + bias[n]
//   sm_103a pass -> tcgen05 ping-pong (TMEM double buffer, epilogue overlap)
//   plain compute_103 -> mma.sync fallback
// ============================================================================
static constexpr int A_HALF    = 128 * BK * 2;            // 16384 (one A m-half)
static constexpr int A_BYTES   = 2 * A_HALF;              // 32768
static constexpr int B_BYTES   = TN * BK * 2;             // 16384
static constexpr int STG_BYTES = A_BYTES + B_BYTES;       // 49152
static constexpr int SMEM_TMEMPTR = 0;
static constexpr int BAR_FULL  = 16;                      // +8s, s<4
static constexpr int BAR_EMPTY = 48;                      // +8s, s<4
static constexpr int BAR_DONE  = 80;                      // +8b, b<2
static constexpr int BAR_EPI   = 96;                      // +8b, b<2
static constexpr int SMEM_TILES = 1024;
static constexpr int GEMM_SMEM = SMEM_TILES + STAGES * STG_BYTES;  // 197632

// idesc for cg1 kind::f16, fp32 accum, M=128, N=128
static constexpr uint32_t GEMM_IDESC_N128 =
    (1u << 4) | ((128 / 8) << 17) | ((128 / 16) << 24);

// ---- fallback constants ----
static constexpr int FB_ROWB   = 144;               // 64 halves + 8 pad, bytes
static constexpr int FB_A_TILE = 256 * FB_ROWB;     // 36864
static constexpr int FB_B_TILE = 128 * FB_ROWB;     // 18432
static constexpr int FB_STAGE  = FB_A_TILE + FB_B_TILE;  // 55296 x2 = 110592

#if !defined(__CUDA_ARCH__) || !defined(__CUDA_ARCH_FEAT_SM103_ALL)
__device__ __forceinline__ void cp_async16(uint32_t dst, const void* src) {
    asm volatile("cp.async.cg.shared.global [%0], [%1], 16;" :: "r"(dst), "l"(src) : "memory");
}
__device__ __forceinline__ void ldsm_x4(uint32_t* r, uint32_t addr) {
    asm volatile("ldmatrix.sync.aligned.m8n8.x4.shared.b16 {%0,%1,%2,%3}, [%4];"
                 : "=r"(r[0]), "=r"(r[1]), "=r"(r[2]), "=r"(r[3]) : "r"(addr));
}
__device__ __forceinline__ void mma16816(float* c, const uint32_t* a, uint32_t b0, uint32_t b1) {
    asm volatile("mma.sync.aligned.m16n8k16.row.col.f32.f16.f16.f32 "
                 "{%0,%1,%2,%3}, {%4,%5,%6,%7}, {%8,%9}, {%0,%1,%2,%3};"
                 : "+f"(c[0]), "+f"(c[1]), "+f"(c[2]), "+f"(c[3])
                 : "r"(a[0]), "r"(a[1]), "r"(a[2]), "r"(a[3]), "r"(b0), "r"(b1));
}
#endif

__global__ void __launch_bounds__(256, 1) lora_gemm_kernel(
    const __grid_constant__ CUtensorMap tmap_a,
    const __grid_constant__ CUtensorMap tmap_b,
    const __half* __restrict__ xh,
    const __half* __restrict__ wh,
    const float* __restrict__ bias,
    float* __restrict__ out)
{
    extern __shared__ __align__(1024) char smem[];
    const uint32_t sb = smem_u32(smem);
    const int tid = threadIdx.x;
    const int wid = tid >> 5;
    const int lane = tid & 31;

#if defined(__CUDA_ARCH_FEAT_SM103_ALL)
    // ================= persistent tcgen05 ping-pong path ====================
    if (wid == 4) {
        TCGEN05_ALLOC(sb + SMEM_TMEMPTR, 512);
        TCGEN05_RELINQUISH();
    }
    if (tid == 0) {
#pragma unroll
        for (int s = 0; s < STAGES; s++) {
            MBARRIER_INIT(sb + BAR_FULL + 8 * s, 1);
            MBARRIER_INIT(sb + BAR_EMPTY + 8 * s, 1);
        }
#pragma unroll
        for (int b = 0; b < 2; b++) {
            MBARRIER_INIT(sb + BAR_DONE + 8 * b, 1);
            MBARRIER_INIT(sb + BAR_EPI + 8 * b, 1);
        }
    }
    __syncthreads();
    TCGEN05_FENCE_AFTER();

    uint32_t tmem;
    asm volatile("ld.shared.b32 %0, [%1];" : "=r"(tmem) : "r"(sb + SMEM_TMEMPTR));

    if (wid == 5) {
        // ---- TMA producer warp ----
        uint32_t elected;
        asm volatile("{\n\t.reg .pred P;\n\telect.sync _|P, 0xFFFFFFFF;\n\tselp.b32 %0, 1, 0, P;\n\t}"
                     : "=r"(elected));
        int s = 0, ph = 1;  // fresh barrier satisfies first wait(parity=1)
        for (int t = blockIdx.x; t < NTILES; t += GRID_X) {
            const int m0 = (t / NT_CNT) * TM;
            const int n0 = (t % NT_CNT) * TN;
            for (int kt = 0; kt < KTILES; kt++) {
                MBARRIER_WAIT_PARITY(sb + BAR_EMPTY + 8 * s, ph);
                if (elected) {
                    uint32_t full = sb + BAR_FULL + 8 * s;
                    MBARRIER_EXPECT_TX(full, STG_BYTES);
                    uint32_t dst = sb + SMEM_TILES + s * STG_BYTES;
                    TMA_LOAD_2D(dst,          &tmap_a, kt * BK, m0,       full);
                    TMA_LOAD_2D(dst + A_HALF, &tmap_a, kt * BK, m0 + 128, full);
                    TMA_LOAD_2D(dst + A_BYTES, &tmap_b, kt * BK, n0,      full);
                }
                if (++s == STAGES) { s = 0; ph ^= 1; }
            }
        }
    } else if (wid == 4) {
        // ---- MMA warp ----
        uint32_t elected;
        asm volatile("{\n\t.reg .pred P;\n\telect.sync _|P, 0xFFFFFFFF;\n\tselp.b32 %0, 1, 0, P;\n\t}"
                     : "=r"(elected));
        int s = 0, ph = 0;
        int i = 0;
        for (int t = blockIdx.x; t < NTILES; t += GRID_X, i++) {
            const int b = i & 1;
            const uint32_t dbase = tmem + b * 256;
            if (i >= 2) {
                // wait epilogue of tile i-2 to free TMEM buffer b
                MBARRIER_WAIT_PARITY(sb + BAR_EPI + 8 * b, ((i >> 1) ^ 1) & 1);
            }
            for (int kt = 0; kt < KTILES; kt++) {
                MBARRIER_WAIT_PARITY(sb + BAR_FULL + 8 * s, ph);
                if (elected) {
                    uint32_t stg = sb + SMEM_TILES + s * STG_BYTES;
                    uint64_t ad0 = MAKE_SMEM_DESC(stg);
                    uint64_t ad1 = MAKE_SMEM_DESC(stg + A_HALF);
                    uint64_t bd  = MAKE_SMEM_DESC(stg + A_BYTES);
                    uint32_t en0 = (kt == 0) ? 0u : 1u;
#pragma unroll
                    for (int j = 0; j < BK / 16; j++) {
                        uint32_t en = (j == 0) ? en0 : 1u;
                        uint32_t zero = 0u;
#define MMA_ONE(doff, adesc) \
                        asm volatile( \
                            "{\n\t.reg .pred p;\n\tsetp.ne.u32 p, %5, 0;\n\t" \
                            "tcgen05.mma.cta_group::1.kind::f16 [%0], %1, %2, %3, {%4, %4, %4, %4}, p;\n\t}" \
                            :: "r"(dbase + (doff)), "l"(adesc), "l"(bd + j * 2), \
                               "r"(GEMM_IDESC_N128), "r"(zero), "r"(en) : "memory")
                        MMA_ONE(0,   ad0 + j * 2);
                        MMA_ONE(128, ad1 + j * 2);
#undef MMA_ONE
                    }
                    TCGEN05_COMMIT(sb + BAR_EMPTY + 8 * s);
                }
                if (++s == STAGES) { s = 0; ph ^= 1; }
            }
            if (elected) {
                TCGEN05_COMMIT(sb + BAR_DONE + 8 * b);  // tile i fully accumulated
            }
        }
    } else if (wid < 4) {
        // ---- epilogue warpgroup (warps 0-3) ----
        int i = 0;
        for (int t = blockIdx.x; t < NTILES; t += GRID_X, i++) {
            const int b = i & 1;
            const int m0 = (t / NT_CNT) * TM;
            const int n0 = (t % NT_CNT) * TN;
            const uint32_t dbase = tmem + b * 256;
            MBARRIER_WAIT_PARITY(sb + BAR_DONE + 8 * b, (i >> 1) & 1);
            TCGEN05_FENCE_AFTER();
#pragma unroll
            for (int mh = 0; mh < 2; mh++) {
                const int row_g = m0 + mh * 128 + wid * 32 + lane;
                float* orow = out + (size_t)row_g * N_DIM + n0;
#pragma unroll
                for (int cb = 0; cb < TN / 32; cb++) {
                    uint32_t r[32];
                    TCGEN05_LD_32X32B_X32(r, dbase + mh * 128 + cb * 32);
                    TCGEN05_WAIT_LD();
#pragma unroll
                    for (int c4 = 0; c4 < 8; c4++) {
                        int col = cb * 32 + c4 * 4;
                        float4 v;
                        v.x = __uint_as_float(r[c4 * 4 + 0]) + __ldg(&bias[n0 + col + 0]);
                        v.y = __uint_as_float(r[c4 * 4 + 1]) + __ldg(&bias[n0 + col + 1]);
                        v.z = __uint_as_float(r[c4 * 4 + 2]) + __ldg(&bias[n0 + col + 2]);
                        v.w = __uint_as_float(r[c4 * 4 + 3]) + __ldg(&bias[n0 + col + 3]);
                        *reinterpret_cast<float4*>(orow + col) = v;
                    }
                }
            }
            TCGEN05_FENCE_BEFORE();
            // all 128 epilogue threads done with this buffer
            asm volatile("bar.sync 1, 128;" ::: "memory");
            if (tid == 0) {
                MBARRIER_ARRIVE(sb + BAR_EPI + 8 * b);
            }
        }
    }

    __syncthreads();
    if (wid == 4) {
        TCGEN05_DEALLOC(tmem, 512);
    }

#else
    // ======================= mma.sync fallback path ==========================
    // Persistent, 256 threads, tile 256x128; 8 warps, warp tile 64x64.
    (void)tmap_a; (void)tmap_b;
    const int wm = (wid >> 1) * 64;
    const int wn = (wid & 1) * 64;
    const int l = lane;
    const int a_r = (l & 7) + ((l >> 3) & 1) * 8;
    const int a_c = (l >> 4) * 8;
    const int b_r = (l & 7) + ((l >> 4) & 1) * 8;
    const int b_c = ((l >> 3) & 1) * 8;

    for (int t = blockIdx.x; t < NTILES; t += GRID_X) {
        const int m0 = (t / NT_CNT) * TM;
        const int n0 = (t % NT_CNT) * TN;
        float acc[4][8][4];
#pragma unroll
        for (int mt = 0; mt < 4; mt++)
#pragma unroll
            for (int nt = 0; nt < 8; nt++)
#pragma unroll
                for (int q = 0; q < 4; q++) acc[mt][nt][q] = 0.0f;

        // preload stage 0
        {
            const __half* ga = xh + (size_t)(m0 + tid) * K_DIM;
            uint32_t da = sb + tid * FB_ROWB;
#pragma unroll
            for (int q = 0; q < 8; q++) cp_async16(da + q * 16, ga + q * 8);
            int brow = tid >> 1, half = tid & 1;
            const __half* gb = wh + (size_t)(n0 + brow) * K_DIM + half * 32;
            uint32_t db = sb + FB_A_TILE + brow * FB_ROWB + half * 64;
#pragma unroll
            for (int q = 0; q < 4; q++) cp_async16(db + q * 16, gb + q * 8);
            asm volatile("cp.async.commit_group;" ::: "memory");
        }

        for (int kt = 0; kt < KTILES; kt++) {
            if (kt + 1 < KTILES) {
                int s = (kt + 1) & 1;
                const __half* ga = xh + (size_t)(m0 + tid) * K_DIM + (kt + 1) * BK;
                uint32_t da = sb + s * FB_STAGE + tid * FB_ROWB;
#pragma unroll
                for (int q = 0; q < 8; q++) cp_async16(da + q * 16, ga + q * 8);
                int brow = tid >> 1, half = tid & 1;
                const __half* gb = wh + (size_t)(n0 + brow) * K_DIM + (kt + 1) * BK + half * 32;
                uint32_t db = sb + s * FB_STAGE + FB_A_TILE + brow * FB_ROWB + half * 64;
#pragma unroll
                for (int q = 0; q < 4; q++) cp_async16(db + q * 16, gb + q * 8);
                asm volatile("cp.async.commit_group;" ::: "memory");
                asm volatile("cp.async.wait_group 1;" ::: "memory");
            } else {
                asm volatile("cp.async.wait_group 0;" ::: "memory");
            }
            __syncthreads();

            uint32_t sA = sb + (kt & 1) * FB_STAGE;
            uint32_t sB = sA + FB_A_TILE;
#pragma unroll
            for (int ks = 0; ks < BK / 16; ks++) {
                uint32_t afrag[4][4];
#pragma unroll
                for (int mt = 0; mt < 4; mt++) {
                    uint32_t addr = sA + (wm + mt * 16 + a_r) * FB_ROWB + (ks * 16 + a_c) * 2;
                    ldsm_x4(afrag[mt], addr);
                }
                uint32_t bfrag[4][4];
#pragma unroll
                for (int p = 0; p < 4; p++) {
                    uint32_t addr = sB + (wn + p * 16 + b_r) * FB_ROWB + (ks * 16 + b_c) * 2;
                    ldsm_x4(bfrag[p], addr);
                }
#pragma unroll
                for (int mt = 0; mt < 4; mt++)
#pragma unroll
                    for (int nt = 0; nt < 8; nt++)
                        mma16816(acc[mt][nt], afrag[mt],
                                 bfrag[nt >> 1][(nt & 1) * 2], bfrag[nt >> 1][(nt & 1) * 2 + 1]);
            }
            __syncthreads();
        }

#pragma unroll
        for (int mt = 0; mt < 4; mt++) {
#pragma unroll
            for (int nt = 0; nt < 8; nt++) {
                int r0 = m0 + wm + mt * 16 + (l >> 2);
                int c0 = n0 + wn + nt * 8 + (l & 3) * 2;
                float bx = __ldg(&bias[c0]);
                float by = __ldg(&bias[c0 + 1]);
                float2 v0 = make_float2(acc[mt][nt][0] + bx, acc[mt][nt][1] + by);
                float2 v1 = make_float2(acc[mt][nt][2] + bx, acc[mt][nt][3] + by);
                *reinterpret_cast<float2*>(&out[(size_t)r0 * N_DIM + c0]) = v0;
                *reinterpret_cast<float2*>(&out[(size_t)(r0 + 8) * N_DIM + c0]) = v1;
            }
        }
        __syncthreads();
    }
#endif
}

// ============================================================================
// Host launch
// ============================================================================
typedef CUresult (*tmap_encode_t)(CUtensorMap*, CUtensorMapDataType, cuuint32_t, void*,
                                  const cuuint64_t*, const cuuint64_t*, const cuuint32_t*,
                                  const cuuint32_t*, CUtensorMapInterleave, CUtensorMapSwizzle,
                                  CUtensorMapL2promotion, CUtensorMapFloatOOBfill);

extern "C" void kernel_launch(void* const* d_in, const int* in_sizes, int n_in,
                              void* d_out, int out_size) {
    (void)in_sizes; (void)n_in; (void)out_size;
    const float* x    = (const float*)d_in[0];
    const float* base = (const float*)d_in[1];
    const float* lA   = (const float*)d_in[2];
    const float* lB   = (const float*)d_in[3];
    const float* bias = (const float*)d_in[4];
    float* out = (float*)d_out;

    void* xh_p = nullptr;
    void* wh_p = nullptr;
    cudaGetSymbolAddress(&xh_p, g_xh);
    cudaGetSymbolAddress(&wh_p, g_wh);

    // 1) x -> fp16
    {
        int n4 = M_DIM * K_DIM / 4;
        int nthreads = n4 / 2;
        convert_x_kernel<<<(nthreads + 255) / 256, 256>>>((const float4*)x, (uint2*)xh_p, n4);
    }
    // 2) W' = base + 2*(B@A) -> fp16
    {
        int n4 = N_DIM * K_DIM / 4;
        build_w_kernel<<<(n4 + 255) / 256, 256>>>((const float4*)base, (const float4*)lA,
                                                  lB, (uint2*)wh_p);
    }

    // 3) tensor maps (A and B boxes 64 x 128 rows)
    static tmap_encode_t encode = nullptr;
    if (!encode) {
        void* pfn = nullptr;
        cudaDriverEntryPointQueryResult qres;
#if CUDART_VERSION >= 12050
        cudaGetDriverEntryPointByVersion("cuTensorMapEncodeTiled", &pfn, 12000,
                                         cudaEnableDefault, &qres);
#else
        cudaGetDriverEntryPoint("cuTensorMapEncodeTiled", &pfn, cudaEnableDefault, &qres);
#endif
        encode = (tmap_encode_t)pfn;
    }

    CUtensorMap mapA{}, mapB{};
    if (encode) {
        {
            cuuint64_t dims[2]    = {K_DIM, M_DIM};
            cuuint64_t strides[1] = {K_DIM * sizeof(__half)};
            cuuint32_t box[2]     = {BK, 128};
            cuuint32_t es[2]      = {1, 1};
            encode(&mapA, CU_TENSOR_MAP_DATA_TYPE_FLOAT16, 2, xh_p, dims, strides, box, es,
                   CU_TENSOR_MAP_INTERLEAVE_NONE, CU_TENSOR_MAP_SWIZZLE_128B,
                   CU_TENSOR_MAP_L2_PROMOTION_L2_128B, CU_TENSOR_MAP_FLOAT_OOB_FILL_NONE);
        }
        {
            cuuint64_t dims[2]    = {K_DIM, N_DIM};
            cuuint64_t strides[1] = {K_DIM * sizeof(__half)};
            cuuint32_t box[2]     = {BK, TN};
            cuuint32_t es[2]      = {1, 1};
            encode(&mapB, CU_TENSOR_MAP_DATA_TYPE_FLOAT16, 2, wh_p, dims, strides, box, es,
                   CU_TENSOR_MAP_INTERLEAVE_NONE, CU_TENSOR_MAP_SWIZZLE_128B,
                   CU_TENSOR_MAP_L2_PROMOTION_L2_128B, CU_TENSOR_MAP_FLOAT_OOB_FILL_NONE);
        }
    }

    cudaFuncSetAttribute(lora_gemm_kernel, cudaFuncAttributeMaxDynamicSharedMemorySize,
                         GEMM_SMEM);
    lora_gemm_kernel<<<GRID_X, 256, GEMM_SMEM>>>(mapA, mapB,
                                                 (const __half*)xh_p, (const __half*)wh_p,
                                                 bias, out);
}